// round 2
// baseline (speedup 1.0000x reference)
#include <cuda_runtime.h>
#include <cstdint>

// ---------------------------------------------------------------------------
// SymbolicEmbeddingBlock — restructured:
//   out[e] = silu( TA[x[i[e]]] + TB[x[j[e]]] + r[e] @ W3 + b )
//   r[e]   = silu( rbf[e] @ W_rbf + b_rbf )
// where TA = (codebook[code_idx].reshape(128,128)) @ W[0:128],
//       TB = table @ W[128:256],  W3 = W[256:384].
// Main GEMM done with tf32 mma.sync.m16n8k8 (fp32 accumulate).
// ---------------------------------------------------------------------------

#define HID 128

static __device__ float g_TA[128 * HID];
static __device__ float g_TB[128 * HID];

__device__ __forceinline__ float silu_f(float x) {
    return x / (1.0f + __expf(-x));
}

__device__ __forceinline__ uint32_t f2tf32(float x) {
    uint32_t u;
    asm("cvt.rna.tf32.f32 %0, %1;" : "=r"(u) : "f"(x));
    return u;
}

// ---------------------------------------------------------------------------
// Kernel A: build table row per type and fold into TA/TB.
// grid = 128 (one CTA per type), block = 256.
// ---------------------------------------------------------------------------
__global__ void prep_kernel(const int* __restrict__ code_idx,
                            const float* __restrict__ codebook,
                            const float* __restrict__ W) {
    __shared__ float row[HID];
    const int t = blockIdx.x;
    const int tid = threadIdx.x;

    if (tid < HID) {
        int p = tid >> 4;   // pattern position (SYMBOL_DIM = 16)
        int s = tid & 15;
        row[tid] = codebook[code_idx[t * 8 + p] * 16 + s];
    }
    __syncthreads();

    // tid < 128 -> TA column tid using W rows [0,128)
    // tid >= 128 -> TB column tid-128 using W rows [128,256)
    const float* Wbase = (tid < HID) ? W : (W + HID * HID);
    const int c = tid & (HID - 1);
    float acc = 0.0f;
#pragma unroll 8
    for (int d = 0; d < HID; ++d)
        acc = fmaf(row[d], Wbase[d * HID + c], acc);

    if (tid < HID) g_TA[t * HID + c] = acc;
    else           g_TB[t * HID + c] = acc;
}

// ---------------------------------------------------------------------------
// Kernel B: per-edge fused r-compute + tf32 GEMM + gather-epilogue.
// block = 256 (8 warps). Warp tile: M=16 edges, N=64 cols (8 n-tiles).
// CTA tile: 128 edges x 64 cols; grid = (E/128, 2 column halves).
// ---------------------------------------------------------------------------
__global__ __launch_bounds__(256, 2)
void edge_kernel(const int* __restrict__ x,
                 const float* __restrict__ rbf,
                 const int* __restrict__ ei,
                 const int* __restrict__ ej,
                 const float* __restrict__ W_rbf,
                 const float* __restrict__ b_rbf,
                 const float* __restrict__ W,
                 const float* __restrict__ bias,
                 float* __restrict__ out,
                 int E) {
    // smem: W3 half (128 x 64, stride 72 -> bank-conflict-free B-frag loads)
    __shared__ float W3s[128 * 72];
    __shared__ float Wrbfs[6 * 128];
    __shared__ float brbfs[128];

    const int tid  = threadIdx.x;
    const int half = blockIdx.y;           // column half: cols [half*64, half*64+64)

    // Stage W3 half (converted to tf32 bit pattern), W_rbf, b_rbf.
    for (int idx = tid; idx < 128 * 64; idx += 256) {
        int k = idx >> 6, n = idx & 63;
        float v = W[(256 + k) * HID + half * 64 + n];
        W3s[k * 72 + n] = __uint_as_float(f2tf32(v));
    }
    for (int idx = tid; idx < 6 * 128; idx += 256) Wrbfs[idx] = W_rbf[idx];
    if (tid < 128) brbfs[tid] = b_rbf[tid];
    __syncthreads();

    const int lane = tid & 31;
    const int warp = tid >> 5;
    const int g    = lane >> 2;   // groupID (A row / B col / D row)
    const int tig  = lane & 3;    // thread-in-group (A col / B row)

    const int e0 = blockIdx.x * 128 + warp * 16 + g;
    const int e1 = e0 + 8;
    const int eS0 = min(e0, E - 1);
    const int eS1 = min(e1, E - 1);

    float rbf0[6], rbf1[6];
#pragma unroll
    for (int m = 0; m < 6; ++m) {
        rbf0[m] = rbf[eS0 * 6 + m];
        rbf1[m] = rbf[eS1 * 6 + m];
    }

    float acc[8][4];
#pragma unroll
    for (int nt = 0; nt < 8; ++nt)
#pragma unroll
        for (int q = 0; q < 4; ++q) acc[nt][q] = 0.0f;

    // K loop: 16 chunks of 8. A-fragment r values computed in-register
    // (each (edge,k) lives in exactly one thread of this warp's A tile).
#pragma unroll 4
    for (int kc = 0; kc < 16; ++kc) {
        const int k0 = kc * 8 + tig;        // a0/a1 k
        const int k1 = k0 + 4;              // a2/a3 k

        float d00 = brbfs[k0], d10 = d00;
        float d01 = brbfs[k1], d11 = d01;
#pragma unroll
        for (int m = 0; m < 6; ++m) {
            float w0 = Wrbfs[m * 128 + k0];
            float w1 = Wrbfs[m * 128 + k1];
            d00 = fmaf(rbf0[m], w0, d00);
            d10 = fmaf(rbf1[m], w0, d10);
            d01 = fmaf(rbf0[m], w1, d01);
            d11 = fmaf(rbf1[m], w1, d11);
        }
        const uint32_t a0 = f2tf32(silu_f(d00));   // (e0, k0)
        const uint32_t a1 = f2tf32(silu_f(d10));   // (e1, k0)
        const uint32_t a2 = f2tf32(silu_f(d01));   // (e0, k1)
        const uint32_t a3 = f2tf32(silu_f(d11));   // (e1, k1)

#pragma unroll
        for (int nt = 0; nt < 8; ++nt) {
            const int n = nt * 8 + g;
            const uint32_t b0 = __float_as_uint(W3s[k0 * 72 + n]);
            const uint32_t b1 = __float_as_uint(W3s[k1 * 72 + n]);
            asm volatile(
                "mma.sync.aligned.m16n8k8.row.col.f32.tf32.tf32.f32 "
                "{%0,%1,%2,%3}, {%4,%5,%6,%7}, {%8,%9}, {%0,%1,%2,%3};\n"
                : "+f"(acc[nt][0]), "+f"(acc[nt][1]),
                  "+f"(acc[nt][2]), "+f"(acc[nt][3])
                : "r"(a0), "r"(a1), "r"(a2), "r"(a3), "r"(b0), "r"(b1));
        }
    }

    // Epilogue: add TA[type_i] + TB[type_j] + bias, silu, store.
    const int ti0 = x[ei[eS0]], tj0 = x[ej[eS0]];
    const int ti1 = x[ei[eS1]], tj1 = x[ej[eS1]];
    const int cbase = half * 64 + 2 * tig;

#pragma unroll
    for (int nt = 0; nt < 8; ++nt) {
        const int c = cbase + nt * 8;
        const float2 bb = *(const float2*)(bias + c);
        if (e0 < E) {
            const float2 ta = *(const float2*)(g_TA + ti0 * HID + c);
            const float2 tb = *(const float2*)(g_TB + tj0 * HID + c);
            float2 o;
            o.x = silu_f(acc[nt][0] + ta.x + tb.x + bb.x);
            o.y = silu_f(acc[nt][1] + ta.y + tb.y + bb.y);
            *(float2*)(out + (long)e0 * HID + c) = o;
        }
        if (e1 < E) {
            const float2 ta = *(const float2*)(g_TA + ti1 * HID + c);
            const float2 tb = *(const float2*)(g_TB + tj1 * HID + c);
            float2 o;
            o.x = silu_f(acc[nt][2] + ta.x + tb.x + bb.x);
            o.y = silu_f(acc[nt][3] + ta.y + tb.y + bb.y);
            *(float2*)(out + (long)e1 * HID + c) = o;
        }
    }
}

// ---------------------------------------------------------------------------
// Launch
// ---------------------------------------------------------------------------
extern "C" void kernel_launch(void* const* d_in, const int* in_sizes, int n_in,
                              void* d_out, int out_size) {
    const int*   x        = (const int*)d_in[0];
    const float* rbf      = (const float*)d_in[1];
    const int*   ei       = (const int*)d_in[2];
    const int*   ej       = (const int*)d_in[3];
    const int*   code_idx = (const int*)d_in[4];
    const float* codebook = (const float*)d_in[5];
    const float* W_rbf    = (const float*)d_in[6];
    const float* b_rbf    = (const float*)d_in[7];
    const float* W        = (const float*)d_in[8];
    const float* bias     = (const float*)d_in[9];
    float*       out      = (float*)d_out;

    const int E = in_sizes[2];   // element count of i

    prep_kernel<<<128, 256>>>(code_idx, codebook, W);

    dim3 grid((E + 127) / 128, 2);
    edge_kernel<<<grid, 256>>>(x, rbf, ei, ej, W_rbf, b_rbf, W, bias, out, E);
}

// round 5
// speedup vs baseline: 1.4494x; 1.4494x over previous
#include <cuda_runtime.h>
#include <cstdint>

// ===========================================================================
// SymbolicEmbeddingBlock — tf32 mma.sync, decoupled produce/consume.
//   out[e] = silu( TA'[x[i[e]]] + TB[x[j[e]]] + r[e] @ W3 )   (bias in TA')
//   r[e]   = silu( rbf[e] @ W_rbf + b_rbf )
// Warp tile M=16 x N=128 (full width: no duplicated A work).
// Phase A: all A-fragments for 8 k-chunks precomputed into registers.
// Phase B: mma loop; B-fragments pre-swizzled per-lane -> 1 LDS.64 per tile.
// ===========================================================================

#define HID 128

static __device__ float  g_TA[128 * HID];              // + bias folded in
static __device__ float  g_TB[128 * HID];
static __device__ float2 g_Bf[16 * 16 * 32];           // [kc][nt][lane] b0,b1

__device__ __forceinline__ uint32_t f2tf32(float x) {
    uint32_t u;
    asm("cvt.rna.tf32.f32 %0, %1;" : "=r"(u) : "f"(x));
    return u;
}
__device__ __forceinline__ float silu_f(float x) {
    return __fdividef(x, 1.0f + __expf(-x));
}

// ---------------------------------------------------------------------------
// prep1: TA = table @ W[0:128] + bias,  TB = table @ W[128:256]
// ---------------------------------------------------------------------------
__global__ void prep_tables(const int* __restrict__ code_idx,
                            const float* __restrict__ codebook,
                            const float* __restrict__ W,
                            const float* __restrict__ bias) {
    __shared__ float row[HID];
    const int t = blockIdx.x, tid = threadIdx.x;
    if (tid < HID) {
        int p = tid >> 4, s = tid & 15;
        row[tid] = codebook[code_idx[t * 8 + p] * 16 + s];
    }
    __syncthreads();
    const float* Wbase = (tid < HID) ? W : (W + HID * HID);
    const int c = tid & (HID - 1);
    float acc = 0.0f;
#pragma unroll 8
    for (int d = 0; d < HID; ++d) acc = fmaf(row[d], Wbase[d * HID + c], acc);
    if (tid < HID) g_TA[t * HID + c] = acc + bias[c];
    else           g_TB[t * HID + c] = acc;
}

// ---------------------------------------------------------------------------
// prep2: per-lane B fragment layout for m16n8k8.row.col tf32.
//   lane l: g=l>>2, tig=l&3.  Bf[kc][nt][l] = { W3[kc*8+tig][nt*8+g],
//                                               W3[kc*8+tig+4][nt*8+g] }
// ---------------------------------------------------------------------------
__global__ void prep_bfrag(const float* __restrict__ W) {
    const int idx = blockIdx.x * 256 + threadIdx.x;        // 0..8191
    const int l = idx & 31, nt = (idx >> 5) & 15, kc = idx >> 9;
    const int g = l >> 2, tig = l & 3;
    const int k = kc * 8 + tig, n = nt * 8 + g;
    float2 v;
    v.x = __uint_as_float(f2tf32(W[(256 + k) * HID + n]) );
    v.y = __uint_as_float(f2tf32(W[(256 + k + 4) * HID + n]));
    g_Bf[idx] = v;
}

// ---------------------------------------------------------------------------
// edge kernel: 256 threads, 8 warps. CTA tile = 128 edges x 128 cols.
// ---------------------------------------------------------------------------
__global__ __launch_bounds__(256, 2)
void edge_kernel(const int* __restrict__ x, const float* __restrict__ rbf,
                 const int* __restrict__ ei, const int* __restrict__ ej,
                 const float* __restrict__ W_rbf, const float* __restrict__ b_rbf,
                 float* __restrict__ out, int E) {
    extern __shared__ char sm[];
    float2* Bf = (float2*)sm;                       // 65536 B
    float4* Wt = (float4*)(sm + 65536);             // [k][2] : w0-3 | w4,w5,b,0

    const int tid = threadIdx.x;

    // Stage Bf (coalesced float4 from prebuilt global) and Wt.
    {
        const float4* gB = (const float4*)g_Bf;
        float4* sB = (float4*)sm;
        for (int i = tid; i < 4096; i += 256) sB[i] = gB[i];
        if (tid < HID) {
            const int k = tid;
            float4 a, b;
            a.x = W_rbf[0 * HID + k]; a.y = W_rbf[1 * HID + k];
            a.z = W_rbf[2 * HID + k]; a.w = W_rbf[3 * HID + k];
            b.x = W_rbf[4 * HID + k]; b.y = W_rbf[5 * HID + k];
            b.z = b_rbf[k];           b.w = 0.0f;
            Wt[k * 2 + 0] = a;
            Wt[k * 2 + 1] = b;
        }
    }
    __syncthreads();

    const int warp = tid >> 5, lane = tid & 31;
    const int g = lane >> 2, tig = lane & 3;

    const long e0 = (long)blockIdx.x * 128 + warp * 16 + g;
    const long e1 = e0 + 8;
    const long eS0 = (e0 < E) ? e0 : (E - 1);
    const long eS1 = (e1 < E) ? e1 : (E - 1);

    float2 r00 = *(const float2*)(rbf + eS0 * 6);
    float2 r01 = *(const float2*)(rbf + eS0 * 6 + 2);
    float2 r02 = *(const float2*)(rbf + eS0 * 6 + 4);
    float2 r10 = *(const float2*)(rbf + eS1 * 6);
    float2 r11 = *(const float2*)(rbf + eS1 * 6 + 2);
    float2 r12 = *(const float2*)(rbf + eS1 * 6 + 4);

    // Prefetch node types early (long-latency gather chain).
    const int ti0 = x[ei[eS0]], tj0 = x[ej[eS0]];
    const int ti1 = x[ei[eS1]], tj1 = x[ej[eS1]];

    float acc[16][4];
#pragma unroll
    for (int nt = 0; nt < 16; ++nt)
#pragma unroll
        for (int q = 0; q < 4; ++q) acc[nt][q] = 0.0f;

#pragma unroll
    for (int ph = 0; ph < 2; ++ph) {
        // ---- phase A: all A-fragments for 8 k-chunks --------------------
        uint32_t Ar[32];
#pragma unroll
        for (int c2 = 0; c2 < 8; ++c2) {
            const int k0 = (ph * 8 + c2) * 8 + tig;
            const float4 wa = Wt[k0 * 2],        wb = Wt[k0 * 2 + 1];
            const float4 va = Wt[(k0 + 4) * 2],  vb = Wt[(k0 + 4) * 2 + 1];

            float d00 = wb.z, d10 = wb.z, d01 = vb.z, d11 = vb.z;
            d00 = fmaf(r00.x, wa.x, d00); d10 = fmaf(r10.x, wa.x, d10);
            d01 = fmaf(r00.x, va.x, d01); d11 = fmaf(r10.x, va.x, d11);
            d00 = fmaf(r00.y, wa.y, d00); d10 = fmaf(r10.y, wa.y, d10);
            d01 = fmaf(r00.y, va.y, d01); d11 = fmaf(r10.y, va.y, d11);
            d00 = fmaf(r01.x, wa.z, d00); d10 = fmaf(r11.x, wa.z, d10);
            d01 = fmaf(r01.x, va.z, d01); d11 = fmaf(r11.x, va.z, d11);
            d00 = fmaf(r01.y, wa.w, d00); d10 = fmaf(r11.y, wa.w, d10);
            d01 = fmaf(r01.y, va.w, d01); d11 = fmaf(r11.y, va.w, d11);
            d00 = fmaf(r02.x, wb.x, d00); d10 = fmaf(r12.x, wb.x, d10);
            d01 = fmaf(r02.x, vb.x, d01); d11 = fmaf(r12.x, vb.x, d11);
            d00 = fmaf(r02.y, wb.y, d00); d10 = fmaf(r12.y, wb.y, d10);
            d01 = fmaf(r02.y, vb.y, d01); d11 = fmaf(r12.y, vb.y, d11);

            Ar[c2 * 4 + 0] = f2tf32(silu_f(d00));
            Ar[c2 * 4 + 1] = f2tf32(silu_f(d10));
            Ar[c2 * 4 + 2] = f2tf32(silu_f(d01));
            Ar[c2 * 4 + 3] = f2tf32(silu_f(d11));
        }

        // ---- phase B: pure mma loop -------------------------------------
#pragma unroll
        for (int c2 = 0; c2 < 8; ++c2) {
            const int kc = ph * 8 + c2;
            const float2* bp = Bf + kc * 512 + lane;
            const uint32_t a0 = Ar[c2 * 4 + 0], a1 = Ar[c2 * 4 + 1];
            const uint32_t a2 = Ar[c2 * 4 + 2], a3 = Ar[c2 * 4 + 3];
#pragma unroll
            for (int nt = 0; nt < 16; ++nt) {
                const float2 b = bp[nt * 32];
                asm volatile(
                    "mma.sync.aligned.m16n8k8.row.col.f32.tf32.tf32.f32 "
                    "{%0,%1,%2,%3}, {%4,%5,%6,%7}, {%8,%9}, {%0,%1,%2,%3};\n"
                    : "+f"(acc[nt][0]), "+f"(acc[nt][1]),
                      "+f"(acc[nt][2]), "+f"(acc[nt][3])
                    : "r"(a0), "r"(a1), "r"(a2), "r"(a3),
                      "r"(__float_as_uint(b.x)), "r"(__float_as_uint(b.y)));
            }
        }
    }

    // ---- epilogue: gather TA'/TB, silu, store ---------------------------
    const float* tA0 = g_TA + ti0 * HID;
    const float* tB0 = g_TB + tj0 * HID;
    const float* tA1 = g_TA + ti1 * HID;
    const float* tB1 = g_TB + tj1 * HID;
    const int cb = 2 * tig;
    float* o0 = out + e0 * HID;
    float* o1 = out + e1 * HID;

#pragma unroll
    for (int nt = 0; nt < 16; ++nt) {
        const int c = nt * 8 + cb;
        if (e0 < E) {
            const float2 ta = *(const float2*)(tA0 + c);
            const float2 tb = *(const float2*)(tB0 + c);
            float2 o;
            o.x = silu_f(acc[nt][0] + ta.x + tb.x);
            o.y = silu_f(acc[nt][1] + ta.y + tb.y);
            *(float2*)(o0 + c) = o;
        }
        if (e1 < E) {
            const float2 ta = *(const float2*)(tA1 + c);
            const float2 tb = *(const float2*)(tB1 + c);
            float2 o;
            o.x = silu_f(acc[nt][2] + ta.x + tb.x);
            o.y = silu_f(acc[nt][3] + ta.y + tb.y);
            *(float2*)(o1 + c) = o;
        }
    }
}

// ---------------------------------------------------------------------------
extern "C" void kernel_launch(void* const* d_in, const int* in_sizes, int n_in,
                              void* d_out, int out_size) {
    const int*   x        = (const int*)d_in[0];
    const float* rbf      = (const float*)d_in[1];
    const int*   ei       = (const int*)d_in[2];
    const int*   ej       = (const int*)d_in[3];
    const int*   code_idx = (const int*)d_in[4];
    const float* codebook = (const float*)d_in[5];
    const float* W_rbf    = (const float*)d_in[6];
    const float* b_rbf    = (const float*)d_in[7];
    const float* W        = (const float*)d_in[8];
    const float* bias     = (const float*)d_in[9];
    float*       out      = (float*)d_out;

    const int E = in_sizes[2];
    const int SMEM = 65536 + 4096;

    static bool attr_set = false;
    if (!attr_set) {
        cudaFuncSetAttribute(edge_kernel,
                             cudaFuncAttributeMaxDynamicSharedMemorySize, SMEM);
        attr_set = true;
    }

    prep_tables<<<128, 256>>>(code_idx, codebook, W, bias);
    prep_bfrag<<<32, 256>>>(W);
    edge_kernel<<<(E + 127) / 128, 256, SMEM>>>(x, rbf, ei, ej, W_rbf, b_rbf,
                                                out, E);
}

// round 6
// speedup vs baseline: 2.1640x; 1.4930x over previous
#include <cuda_runtime.h>
#include <cstdint>

// ===========================================================================
// SymbolicEmbeddingBlock — tf32 mma.sync, SMEM A-fragment handoff.
//   out[e] = silu( TA'[x[i[e]]] + TB[x[j[e]]] + r[e] @ W3 )   (bias in TA')
//   r[e]   = silu( rbf[e] @ W_rbf + b_rbf )
// CTA tile = 256 edges x 128 cols, 512 threads, 1 CTA/SM (200 KB smem).
// Phase 1: all threads produce A-fragments (tf32) into SMEM Af.
// Phase 2: warp tile M=32 x N=64; A via LDS.128, B via LDS.64; mma.sync.
// ===========================================================================

#define HID    128
#define TILE_E 256

static __device__ float  g_TA[128 * HID];      // bias folded in
static __device__ float  g_TB[128 * HID];
static __device__ float2 g_Bf[16 * 16 * 32];   // [kc][nt][lane] {b0,b1}

__device__ __forceinline__ uint32_t f2tf32(float x) {
    uint32_t u;
    asm("cvt.rna.tf32.f32 %0, %1;" : "=r"(u) : "f"(x));
    return u;
}
__device__ __forceinline__ float silu_f(float x) {
    return __fdividef(x, 1.0f + __expf(-x));
}

// ---------------------------------------------------------------------------
// prep (merged): blocks 0-127 -> TA/TB tables; blocks 128-159 -> B fragments.
// ---------------------------------------------------------------------------
__global__ void prep_kernel(const int* __restrict__ code_idx,
                            const float* __restrict__ codebook,
                            const float* __restrict__ W,
                            const float* __restrict__ bias) {
    const int tid = threadIdx.x;
    if (blockIdx.x >= 128) {
        const int idx = (blockIdx.x - 128) * 256 + tid;     // 0..8191
        const int l = idx & 31, nt = (idx >> 5) & 15, kc = idx >> 9;
        const int g = l >> 2, tg = l & 3;
        const int k = kc * 8 + tg, n = nt * 8 + g;
        float2 v;
        v.x = __uint_as_float(f2tf32(W[(256 + k) * HID + n]));
        v.y = __uint_as_float(f2tf32(W[(256 + k + 4) * HID + n]));
        g_Bf[idx] = v;
        return;
    }
    __shared__ float row[HID];
    const int t = blockIdx.x;
    if (tid < HID) {
        int p = tid >> 4, s2 = tid & 15;
        row[tid] = codebook[code_idx[t * 8 + p] * 16 + s2];
    }
    __syncthreads();
    const float* Wb = (tid < HID) ? W : (W + HID * HID);
    const int c = tid & (HID - 1);
    float a0 = 0.0f, a1 = 0.0f;
#pragma unroll
    for (int d = 0; d < HID; d += 2) {
        a0 = fmaf(row[d],     Wb[d * HID + c],       a0);
        a1 = fmaf(row[d + 1], Wb[(d + 1) * HID + c], a1);
    }
    const float acc = a0 + a1;
    if (tid < HID) g_TA[t * HID + c] = acc + bias[c];
    else           g_TB[t * HID + c] = acc;
}

// ---------------------------------------------------------------------------
// edge kernel
// ---------------------------------------------------------------------------
__global__ __launch_bounds__(512, 1)
void edge_kernel(const int* __restrict__ x, const float* __restrict__ rbf,
                 const int* __restrict__ ei, const int* __restrict__ ej,
                 const float* __restrict__ W_rbf, const float* __restrict__ b_rbf,
                 float* __restrict__ out, int E) {
    extern __shared__ char sm[];
    uint4*  Af = (uint4*)sm;                   // [mblk16][kc16][lane32] : 131072
    float2* Bf = (float2*)(sm + 131072);       // [kc16][nt16][lane32]  : 65536
    float4* Wt = (float4*)(sm + 196608);       // [k128][2]             : 4096

    const int tid = threadIdx.x, lane = tid & 31, s = tid >> 5;
    const int g = lane >> 2, tig = lane & 3;

    // ---- stage Bf + Wt ----------------------------------------------------
    {
        const float4* gB = (const float4*)g_Bf;
        float4* sB = (float4*)(sm + 131072);
#pragma unroll
        for (int i = 0; i < 8; ++i) sB[tid + i * 512] = gB[tid + i * 512];
        if (tid < HID) {
            const int k = tid;
            float4 a, b;
            a.x = W_rbf[0 * HID + k]; a.y = W_rbf[1 * HID + k];
            a.z = W_rbf[2 * HID + k]; a.w = W_rbf[3 * HID + k];
            b.x = W_rbf[4 * HID + k]; b.y = W_rbf[5 * HID + k];
            b.z = b_rbf[k];           b.w = 0.0f;
            Wt[k * 2 + 0] = a;
            Wt[k * 2 + 1] = b;
        }
    }

    const long base = (long)blockIdx.x * TILE_E;

    // phase-1 edges: this thread produces A-frags for m-block s
    const long pA = base + s * 16 + g, pB = pA + 8;
    const long pAs = (pA < E) ? pA : (E - 1);
    const long pBs = (pB < E) ? pB : (E - 1);
    const float2 r00 = *(const float2*)(rbf + pAs * 6);
    const float2 r01 = *(const float2*)(rbf + pAs * 6 + 2);
    const float2 r02 = *(const float2*)(rbf + pAs * 6 + 4);
    const float2 r10 = *(const float2*)(rbf + pBs * 6);
    const float2 r11 = *(const float2*)(rbf + pBs * 6 + 2);
    const float2 r12 = *(const float2*)(rbf + pBs * 6 + 4);

    // phase-2 edges: warp covers m-blocks {2u, 2u+1}, column half sh
    const int u = s & 7, sh = s >> 3;
    long ev[4]; int ti[4], tj[4];
#pragma unroll
    for (int q = 0; q < 4; ++q) {
        ev[q] = base + (2 * u + (q >> 1)) * 16 + g + 8 * (q & 1);
        const long es = (ev[q] < E) ? ev[q] : (E - 1);
        ti[q] = x[ei[es]];
        tj[q] = x[ej[es]];
    }
    __syncthreads();

    // ---- phase 1: produce A-fragments into Af ----------------------------
#pragma unroll
    for (int kc = 0; kc < 16; ++kc) {
        const int k0 = kc * 8 + tig;
        const float4 wa = Wt[k0 * 2],       wb = Wt[k0 * 2 + 1];
        const float4 va = Wt[(k0 + 4) * 2], vb = Wt[(k0 + 4) * 2 + 1];

        float d00 = wb.z, d10 = wb.z, d01 = vb.z, d11 = vb.z;
        d00 = fmaf(r00.x, wa.x, d00); d10 = fmaf(r10.x, wa.x, d10);
        d01 = fmaf(r00.x, va.x, d01); d11 = fmaf(r10.x, va.x, d11);
        d00 = fmaf(r00.y, wa.y, d00); d10 = fmaf(r10.y, wa.y, d10);
        d01 = fmaf(r00.y, va.y, d01); d11 = fmaf(r10.y, va.y, d11);
        d00 = fmaf(r01.x, wa.z, d00); d10 = fmaf(r11.x, wa.z, d10);
        d01 = fmaf(r01.x, va.z, d01); d11 = fmaf(r11.x, va.z, d11);
        d00 = fmaf(r01.y, wa.w, d00); d10 = fmaf(r11.y, wa.w, d10);
        d01 = fmaf(r01.y, va.w, d01); d11 = fmaf(r11.y, va.w, d11);
        d00 = fmaf(r02.x, wb.x, d00); d10 = fmaf(r12.x, wb.x, d10);
        d01 = fmaf(r02.x, vb.x, d01); d11 = fmaf(r12.x, vb.x, d11);
        d00 = fmaf(r02.y, wb.y, d00); d10 = fmaf(r12.y, wb.y, d10);
        d01 = fmaf(r02.y, vb.y, d01); d11 = fmaf(r12.y, vb.y, d11);

        Af[(s * 16 + kc) * 32 + lane] = make_uint4(
            f2tf32(silu_f(d00)), f2tf32(silu_f(d10)),
            f2tf32(silu_f(d01)), f2tf32(silu_f(d11)));
    }
    __syncthreads();

    // ---- phase 2: M=32 x N=64 mma loop -----------------------------------
    float acc[2][8][4];
#pragma unroll
    for (int mb = 0; mb < 2; ++mb)
#pragma unroll
        for (int nt = 0; nt < 8; ++nt)
#pragma unroll
            for (int q = 0; q < 4; ++q) acc[mb][nt][q] = 0.0f;

#pragma unroll
    for (int kc = 0; kc < 16; ++kc) {
        const uint4 A0 = Af[((2 * u + 0) * 16 + kc) * 32 + lane];
        const uint4 A1 = Af[((2 * u + 1) * 16 + kc) * 32 + lane];
        const float2* bp = Bf + (kc * 16 + sh * 8) * 32 + lane;
#pragma unroll
        for (int nt = 0; nt < 8; ++nt) {
            const float2 b = bp[nt * 32];
            const uint32_t b0 = __float_as_uint(b.x);
            const uint32_t b1 = __float_as_uint(b.y);
            asm volatile(
                "mma.sync.aligned.m16n8k8.row.col.f32.tf32.tf32.f32 "
                "{%0,%1,%2,%3}, {%4,%5,%6,%7}, {%8,%9}, {%0,%1,%2,%3};\n"
                : "+f"(acc[0][nt][0]), "+f"(acc[0][nt][1]),
                  "+f"(acc[0][nt][2]), "+f"(acc[0][nt][3])
                : "r"(A0.x), "r"(A0.y), "r"(A0.z), "r"(A0.w), "r"(b0), "r"(b1));
            asm volatile(
                "mma.sync.aligned.m16n8k8.row.col.f32.tf32.tf32.f32 "
                "{%0,%1,%2,%3}, {%4,%5,%6,%7}, {%8,%9}, {%0,%1,%2,%3};\n"
                : "+f"(acc[1][nt][0]), "+f"(acc[1][nt][1]),
                  "+f"(acc[1][nt][2]), "+f"(acc[1][nt][3])
                : "r"(A1.x), "r"(A1.y), "r"(A1.z), "r"(A1.w), "r"(b0), "r"(b1));
        }
    }

    // ---- epilogue: gather TA'/TB, silu, store ----------------------------
    const int cb = sh * 64 + 2 * tig;
#pragma unroll
    for (int q = 0; q < 4; ++q) {
        const int mb = q >> 1, h = q & 1;
        if (ev[q] < E) {
            const float* tAq = g_TA + ti[q] * HID;
            const float* tBq = g_TB + tj[q] * HID;
            float* orow = out + ev[q] * HID;
#pragma unroll
            for (int nt = 0; nt < 8; ++nt) {
                const int c = cb + nt * 8;
                const float2 ta = *(const float2*)(tAq + c);
                const float2 tb = *(const float2*)(tBq + c);
                float2 o;
                o.x = silu_f(acc[mb][nt][2 * h + 0] + ta.x + tb.x);
                o.y = silu_f(acc[mb][nt][2 * h + 1] + ta.y + tb.y);
                *(float2*)(orow + c) = o;
            }
        }
    }
}

// ---------------------------------------------------------------------------
extern "C" void kernel_launch(void* const* d_in, const int* in_sizes, int n_in,
                              void* d_out, int out_size) {
    const int*   x        = (const int*)d_in[0];
    const float* rbf      = (const float*)d_in[1];
    const int*   ei       = (const int*)d_in[2];
    const int*   ej       = (const int*)d_in[3];
    const int*   code_idx = (const int*)d_in[4];
    const float* codebook = (const float*)d_in[5];
    const float* W_rbf    = (const float*)d_in[6];
    const float* b_rbf    = (const float*)d_in[7];
    const float* W        = (const float*)d_in[8];
    const float* bias     = (const float*)d_in[9];
    float*       out      = (float*)d_out;

    const int E = in_sizes[2];
    const int SMEM = 131072 + 65536 + 4096;   // 200704

    static bool attr_set = false;
    if (!attr_set) {
        cudaFuncSetAttribute(edge_kernel,
                             cudaFuncAttributeMaxDynamicSharedMemorySize, SMEM);
        attr_set = true;
    }

    prep_kernel<<<160, 256>>>(code_idx, codebook, W, bias);
    edge_kernel<<<(E + TILE_E - 1) / TILE_E, 512, SMEM>>>(x, rbf, ei, ej,
                                                          W_rbf, b_rbf, out, E);
}

// round 8
// speedup vs baseline: 2.3452x; 1.0837x over previous
#include <cuda_runtime.h>
#include <cstdint>

// ===========================================================================
// SymbolicEmbeddingBlock — tf32 mma.sync, SMEM A-handoff + row-major epilogue.
//   out[e] = silu( TA'[x[i[e]]] + TB[x[j[e]]] + r[e] @ W3 )   (bias in TA')
//   r[e]   = silu( rbf[e] @ W_rbf + b_rbf )
// CTA tile = 256 edges x 128 cols, 512 threads, 1 CTA/SM.
// Phase 1: all threads produce A-fragments (tf32) into SMEM Af.
// Phase 2: warp tile M=32 x N=64 mma loop; acc dumped to SMEM (row-major).
// Phase 3: epilogue, 1 warp : 1 edge-row -> fully coalesced gathers/stores.
// ===========================================================================

#define HID    128
#define TILE_E 256
#define RS     132                      // acc row stride (floats), 16B-aligned

static __device__ float  g_TA[128 * HID];      // bias folded in
static __device__ float  g_TB[128 * HID];
static __device__ float2 g_Bf[16 * 16 * 32];   // [kc][nt][lane] {b0,b1}

// SMEM offsets (bytes)
#define AF_OFF   0                      // A-frags 128K  | acc 256*132*4=135168
#define BF_OFF   135168                 // 65536
#define WT_OFF   200704                 // 4096
#define TY_OFF   204800                 // 2048 (tyI[256], tyJ[256])
#define SMEM_SZ  206848

__device__ __forceinline__ uint32_t f2tf32(float x) {
    uint32_t u;
    asm("cvt.rna.tf32.f32 %0, %1;" : "=r"(u) : "f"(x));
    return u;
}
__device__ __forceinline__ float silu_f(float x) {
    return __fdividef(x, 1.0f + __expf(-x));
}

// ---------------------------------------------------------------------------
// prep (merged): blocks 0-127 -> TA/TB tables; blocks 128-159 -> B fragments.
// ---------------------------------------------------------------------------
__global__ void prep_kernel(const int* __restrict__ code_idx,
                            const float* __restrict__ codebook,
                            const float* __restrict__ W,
                            const float* __restrict__ bias) {
    const int tid = threadIdx.x;
    if (blockIdx.x >= 128) {
        const int idx = (blockIdx.x - 128) * 256 + tid;     // 0..8191
        const int l = idx & 31, nt = (idx >> 5) & 15, kc = idx >> 9;
        const int g = l >> 2, tg = l & 3;
        const int k = kc * 8 + tg, n = nt * 8 + g;
        float2 v;
        v.x = __uint_as_float(f2tf32(W[(256 + k) * HID + n]));
        v.y = __uint_as_float(f2tf32(W[(256 + k + 4) * HID + n]));
        g_Bf[idx] = v;
        return;
    }
    __shared__ float row[HID];
    const int t = blockIdx.x;
    if (tid < HID) {
        int p = tid >> 4, s2 = tid & 15;
        row[tid] = codebook[code_idx[t * 8 + p] * 16 + s2];
    }
    __syncthreads();
    const float* Wb = (tid < HID) ? W : (W + HID * HID);
    const int c = tid & (HID - 1);
    float a0 = 0.0f, a1 = 0.0f;
#pragma unroll
    for (int d = 0; d < HID; d += 2) {
        a0 = fmaf(row[d],     Wb[d * HID + c],       a0);
        a1 = fmaf(row[d + 1], Wb[(d + 1) * HID + c], a1);
    }
    const float acc = a0 + a1;
    if (tid < HID) g_TA[t * HID + c] = acc + bias[c];
    else           g_TB[t * HID + c] = acc;
}

// ---------------------------------------------------------------------------
// edge kernel
// ---------------------------------------------------------------------------
__global__ __launch_bounds__(512, 1)
void edge_kernel(const int* __restrict__ x, const float* __restrict__ rbf,
                 const int* __restrict__ ei, const int* __restrict__ ej,
                 const float* __restrict__ W_rbf, const float* __restrict__ b_rbf,
                 float* __restrict__ out, int E) {
    extern __shared__ char sm[];
    uint4*  Af   = (uint4*)(sm + AF_OFF);    // [mblk16][kc16][lane32]
    float*  accS = (float*)(sm + AF_OFF);    // [256][RS]   (aliases Af)
    float2* Bf   = (float2*)(sm + BF_OFF);   // [kc16][nt16][lane32]
    float4* Wt   = (float4*)(sm + WT_OFF);   // [k128][2]
    int*    tyI  = (int*)(sm + TY_OFF);
    int*    tyJ  = (int*)(sm + TY_OFF + 1024);

    const int tid = threadIdx.x, lane = tid & 31, s = tid >> 5;
    const int g = lane >> 2, tig = lane & 3;
    const long base = (long)blockIdx.x * TILE_E;

    // ---- stage Bf + Wt + node types --------------------------------------
    {
        const float4* gB = (const float4*)g_Bf;
        float4* sB = (float4*)(sm + BF_OFF);
#pragma unroll
        for (int i = 0; i < 8; ++i) sB[tid + i * 512] = gB[tid + i * 512];
        if (tid < HID) {
            const int k = tid;
            float4 a, b;
            a.x = W_rbf[0 * HID + k]; a.y = W_rbf[1 * HID + k];
            a.z = W_rbf[2 * HID + k]; a.w = W_rbf[3 * HID + k];
            b.x = W_rbf[4 * HID + k]; b.y = W_rbf[5 * HID + k];
            b.z = b_rbf[k];           b.w = 0.0f;
            Wt[k * 2 + 0] = a;
            Wt[k * 2 + 1] = b;
        }
        if (tid < TILE_E) {
            long e = base + tid;
            if (e >= E) e = E - 1;
            tyI[tid] = x[ei[e]];
            tyJ[tid] = x[ej[e]];
        }
    }

    // phase-1 edges: this thread produces A-frags for m-block s
    const long pA = base + s * 16 + g, pB = pA + 8;
    const long pAs = (pA < E) ? pA : (E - 1);
    const long pBs = (pB < E) ? pB : (E - 1);
    const float2 r00 = *(const float2*)(rbf + pAs * 6);
    const float2 r01 = *(const float2*)(rbf + pAs * 6 + 2);
    const float2 r02 = *(const float2*)(rbf + pAs * 6 + 4);
    const float2 r10 = *(const float2*)(rbf + pBs * 6);
    const float2 r11 = *(const float2*)(rbf + pBs * 6 + 2);
    const float2 r12 = *(const float2*)(rbf + pBs * 6 + 4);
    __syncthreads();

    // ---- phase 1: produce A-fragments into Af ----------------------------
#pragma unroll
    for (int kc = 0; kc < 16; ++kc) {
        const int k0 = kc * 8 + tig;
        const float4 wa = Wt[k0 * 2],       wb = Wt[k0 * 2 + 1];
        const float4 va = Wt[(k0 + 4) * 2], vb = Wt[(k0 + 4) * 2 + 1];

        float d00 = wb.z, d10 = wb.z, d01 = vb.z, d11 = vb.z;
        d00 = fmaf(r00.x, wa.x, d00); d10 = fmaf(r10.x, wa.x, d10);
        d01 = fmaf(r00.x, va.x, d01); d11 = fmaf(r10.x, va.x, d11);
        d00 = fmaf(r00.y, wa.y, d00); d10 = fmaf(r10.y, wa.y, d10);
        d01 = fmaf(r00.y, va.y, d01); d11 = fmaf(r10.y, va.y, d11);
        d00 = fmaf(r01.x, wa.z, d00); d10 = fmaf(r11.x, wa.z, d10);
        d01 = fmaf(r01.x, va.z, d01); d11 = fmaf(r11.x, va.z, d11);
        d00 = fmaf(r01.y, wa.w, d00); d10 = fmaf(r11.y, wa.w, d10);
        d01 = fmaf(r01.y, va.w, d01); d11 = fmaf(r11.y, va.w, d11);
        d00 = fmaf(r02.x, wb.x, d00); d10 = fmaf(r12.x, wb.x, d10);
        d01 = fmaf(r02.x, vb.x, d01); d11 = fmaf(r12.x, vb.x, d11);
        d00 = fmaf(r02.y, wb.y, d00); d10 = fmaf(r12.y, wb.y, d10);
        d01 = fmaf(r02.y, vb.y, d01); d11 = fmaf(r12.y, vb.y, d11);

        Af[(s * 16 + kc) * 32 + lane] = make_uint4(
            f2tf32(silu_f(d00)), f2tf32(silu_f(d10)),
            f2tf32(silu_f(d01)), f2tf32(silu_f(d11)));
    }
    __syncthreads();

    // ---- phase 2: M=32 x N=64 mma loop -----------------------------------
    const int u = s & 7, sh = s >> 3;
    float acc[2][8][4];
#pragma unroll
    for (int mb = 0; mb < 2; ++mb)
#pragma unroll
        for (int nt = 0; nt < 8; ++nt)
#pragma unroll
            for (int q = 0; q < 4; ++q) acc[mb][nt][q] = 0.0f;

#pragma unroll
    for (int kc = 0; kc < 16; ++kc) {
        const uint4 A0 = Af[((2 * u + 0) * 16 + kc) * 32 + lane];
        const uint4 A1 = Af[((2 * u + 1) * 16 + kc) * 32 + lane];
        const float2* bp = Bf + (kc * 16 + sh * 8) * 32 + lane;
#pragma unroll
        for (int nt = 0; nt < 8; ++nt) {
            const float2 b = bp[nt * 32];
            const uint32_t b0 = __float_as_uint(b.x);
            const uint32_t b1 = __float_as_uint(b.y);
            asm volatile(
                "mma.sync.aligned.m16n8k8.row.col.f32.tf32.tf32.f32 "
                "{%0,%1,%2,%3}, {%4,%5,%6,%7}, {%8,%9}, {%0,%1,%2,%3};\n"
                : "+f"(acc[0][nt][0]), "+f"(acc[0][nt][1]),
                  "+f"(acc[0][nt][2]), "+f"(acc[0][nt][3])
                : "r"(A0.x), "r"(A0.y), "r"(A0.z), "r"(A0.w), "r"(b0), "r"(b1));
            asm volatile(
                "mma.sync.aligned.m16n8k8.row.col.f32.tf32.tf32.f32 "
                "{%0,%1,%2,%3}, {%4,%5,%6,%7}, {%8,%9}, {%0,%1,%2,%3};\n"
                : "+f"(acc[1][nt][0]), "+f"(acc[1][nt][1]),
                  "+f"(acc[1][nt][2]), "+f"(acc[1][nt][3])
                : "r"(A1.x), "r"(A1.y), "r"(A1.z), "r"(A1.w), "r"(b0), "r"(b1));
        }
    }
    __syncthreads();      // Af fully consumed; safe to overwrite with acc

    // ---- dump acc to SMEM (row-major, stride RS) -------------------------
#pragma unroll
    for (int mb = 0; mb < 2; ++mb)
#pragma unroll
        for (int h = 0; h < 2; ++h) {
            const int row = (2 * u + mb) * 16 + g + 8 * h;
#pragma unroll
            for (int nt = 0; nt < 8; ++nt) {
                const int col = sh * 64 + nt * 8 + 2 * tig;
                *(float2*)(accS + row * RS + col) =
                    make_float2(acc[mb][nt][2 * h], acc[mb][nt][2 * h + 1]);
            }
        }
    __syncthreads();

    // ---- phase 3: row-major epilogue (1 warp : 1 edge) -------------------
#pragma unroll 2
    for (int it = 0; it < 16; ++it) {
        const int el = s * 16 + it;                 // 0..255
        const long e = base + el;
        const float4 av = *(const float4*)(accS + el * RS + lane * 4);
        const float4 ta = *(const float4*)(g_TA + tyI[el] * HID + lane * 4);
        const float4 tb = *(const float4*)(g_TB + tyJ[el] * HID + lane * 4);
        float4 o;
        o.x = silu_f(av.x + ta.x + tb.x);
        o.y = silu_f(av.y + ta.y + tb.y);
        o.z = silu_f(av.z + ta.z + tb.z);
        o.w = silu_f(av.w + ta.w + tb.w);
        if (e < E) *(float4*)(out + e * HID + lane * 4) = o;
    }
}

// ---------------------------------------------------------------------------
extern "C" void kernel_launch(void* const* d_in, const int* in_sizes, int n_in,
                              void* d_out, int out_size) {
    const int*   x        = (const int*)d_in[0];
    const float* rbf      = (const float*)d_in[1];
    const int*   ei       = (const int*)d_in[2];
    const int*   ej       = (const int*)d_in[3];
    const int*   code_idx = (const int*)d_in[4];
    const float* codebook = (const float*)d_in[5];
    const float* W_rbf    = (const float*)d_in[6];
    const float* b_rbf    = (const float*)d_in[7];
    const float* W        = (const float*)d_in[8];
    const float* bias     = (const float*)d_in[9];
    float*       out      = (float*)d_out;

    const int E = in_sizes[2];

    static bool attr_set = false;
    if (!attr_set) {
        cudaFuncSetAttribute(edge_kernel,
                             cudaFuncAttributeMaxDynamicSharedMemorySize, SMEM_SZ);
        attr_set = true;
    }

    prep_kernel<<<160, 256>>>(code_idx, codebook, W, bias);
    edge_kernel<<<(E + TILE_E - 1) / TILE_E, 512, SMEM_SZ>>>(x, rbf, ei, ej,
                                                             W_rbf, b_rbf, out, E);
}

// round 10
// speedup vs baseline: 2.8040x; 1.1956x over previous
#include <cuda_runtime.h>
#include <cstdint>

// ===========================================================================
// SymbolicEmbeddingBlock — tf32 mma.sync, register A-frags, 2 CTAs/SM.
//   out[e] = silu( TA'[x[i[e]]] + TB[x[j[e]]] + r[e] @ W3 )   (bias in TA')
//   r[e]   = silu( rbf[e] @ W_rbf + b_rbf )        (phase-1 silu: tanh.approx)
// CTA tile = 128 edges x 128 cols, 256 threads, 2 CTAs/SM (69 KB smem).
// Warp tile M=32 x N=64; A-fragments computed in registers, 1-deep pipeline.
// acc dumped into the dead Bf region (XOR row swizzle) -> coalesced epilogue.
// ===========================================================================

#define HID    128
#define TILE_E 128

static __device__ float  g_TA[128 * HID];      // bias folded in
static __device__ float  g_TB[128 * HID];
static __device__ float2 g_Bf[16 * 16 * 32];   // [kc][nt][lane] {b0,b1}

// SMEM map (bytes). accS aliases Bf exactly; Wt/ty never overlapped.
#define BF_OFF   0                      // 65536
#define WT_OFF   65536                  // 4096
#define TY_OFF   69632                  // tyI[128], tyJ[128] : 1024
#define SMEM_SZ  70656

__device__ __forceinline__ uint32_t f2tf32(float x) {
    uint32_t u;
    asm("cvt.rna.tf32.f32 %0, %1;" : "=r"(u) : "f"(x));
    return u;
}
__device__ __forceinline__ float silu_exact(float x) {
    return __fdividef(x, 1.0f + __expf(-x));
}
__device__ __forceinline__ float silu_tanh(float x) {    // 1 MUFU
    float h = 0.5f * x, t;
    asm("tanh.approx.f32 %0, %1;" : "=f"(t) : "f"(h));
    return fmaf(h, t, h);
}

// ---------------------------------------------------------------------------
// prep (merged): blocks 0-127 -> TA/TB tables; blocks 128-159 -> B fragments.
// ---------------------------------------------------------------------------
__global__ void prep_kernel(const int* __restrict__ code_idx,
                            const float* __restrict__ codebook,
                            const float* __restrict__ W,
                            const float* __restrict__ bias) {
    const int tid = threadIdx.x;
    if (blockIdx.x >= 128) {
        const int idx = (blockIdx.x - 128) * 256 + tid;     // 0..8191
        const int l = idx & 31, nt = (idx >> 5) & 15, kc = idx >> 9;
        const int g = l >> 2, tg = l & 3;
        const int k = kc * 8 + tg, n = nt * 8 + g;
        float2 v;
        v.x = __uint_as_float(f2tf32(W[(256 + k) * HID + n]));
        v.y = __uint_as_float(f2tf32(W[(256 + k + 4) * HID + n]));
        g_Bf[idx] = v;
        return;
    }
    __shared__ float row[HID];
    const int t = blockIdx.x;
    if (tid < HID) {
        int p = tid >> 4, s2 = tid & 15;
        row[tid] = codebook[code_idx[t * 8 + p] * 16 + s2];
    }
    __syncthreads();
    const float* Wb = (tid < HID) ? W : (W + HID * HID);
    const int c = tid & (HID - 1);
    float a0 = 0.f, a1 = 0.f, a2 = 0.f, a3 = 0.f;
#pragma unroll
    for (int d = 0; d < HID; d += 4) {
        a0 = fmaf(row[d],     Wb[(d)     * HID + c], a0);
        a1 = fmaf(row[d + 1], Wb[(d + 1) * HID + c], a1);
        a2 = fmaf(row[d + 2], Wb[(d + 2) * HID + c], a2);
        a3 = fmaf(row[d + 3], Wb[(d + 3) * HID + c], a3);
    }
    const float acc = (a0 + a1) + (a2 + a3);
    if (tid < HID) g_TA[t * HID + c] = acc + bias[c];
    else           g_TB[t * HID + c] = acc;
}

// ---------------------------------------------------------------------------
// edge kernel: 256 threads, 8 warps, 2 CTAs/SM.
// ---------------------------------------------------------------------------
__global__ __launch_bounds__(256, 2)
void edge_kernel(const int* __restrict__ x, const float* __restrict__ rbf,
                 const int* __restrict__ ei, const int* __restrict__ ej,
                 const float* __restrict__ W_rbf, const float* __restrict__ b_rbf,
                 float* __restrict__ out, int E) {
    extern __shared__ char sm[];
    float2* Bf   = (float2*)(sm + BF_OFF);
    float4* Wt   = (float4*)(sm + WT_OFF);
    float*  accS = (float*)(sm + BF_OFF);   // aliases Bf ONLY, used after sync
    int*    tyI  = (int*)(sm + TY_OFF);
    int*    tyJ  = (int*)(sm + TY_OFF + 512);

    const int tid = threadIdx.x, lane = tid & 31, w = tid >> 5;
    const int g = lane >> 2, tig = lane & 3;
    const int u = w & 3, sh = w >> 2;
    const int base = blockIdx.x * TILE_E;

    // ---- stage Bf + Wt + node types --------------------------------------
    {
        const float4* gB = (const float4*)g_Bf;
        float4* sB = (float4*)(sm + BF_OFF);
#pragma unroll
        for (int i = 0; i < 16; ++i) sB[tid + i * 256] = gB[tid + i * 256];
        if (tid < HID) {
            const int k = tid;
            float4 a, b;
            a.x = W_rbf[0 * HID + k]; a.y = W_rbf[1 * HID + k];
            a.z = W_rbf[2 * HID + k]; a.w = W_rbf[3 * HID + k];
            b.x = W_rbf[4 * HID + k]; b.y = W_rbf[5 * HID + k];
            b.z = b_rbf[k];           b.w = 0.0f;
            Wt[k * 2 + 0] = a;
            Wt[k * 2 + 1] = b;
        }
        if (tid < TILE_E) {
            int e = base + tid;
            if (e >= E) e = E - 1;
            tyI[tid] = x[ei[e]];
            tyJ[tid] = x[ej[e]];
        }
    }

    // this thread's 4 edges (rows g, g+8 of m-blocks 2u, 2u+1)
    float rb[4][6];
#pragma unroll
    for (int q = 0; q < 4; ++q) {
        int e = base + u * 32 + g + q * 8;
        if (e >= E) e = E - 1;
        const float2 p0 = *(const float2*)(rbf + e * 6);
        const float2 p1 = *(const float2*)(rbf + e * 6 + 2);
        const float2 p2 = *(const float2*)(rbf + e * 6 + 4);
        rb[q][0] = p0.x; rb[q][1] = p0.y; rb[q][2] = p1.x;
        rb[q][3] = p1.y; rb[q][4] = p2.x; rb[q][5] = p2.y;
    }
    __syncthreads();

    // ---- main loop: pipelined A-compute + mma ----------------------------
    float acc[2][8][4];
#pragma unroll
    for (int mb = 0; mb < 2; ++mb)
#pragma unroll
        for (int nt = 0; nt < 8; ++nt)
#pragma unroll
            for (int q = 0; q < 4; ++q) acc[mb][nt][q] = 0.0f;

    uint32_t Ac0[4], Ac1[4];

    // A-fragment compute, manually inlined (macro-free, no array params)
#define COMPUTE_A(KC, D0, D1)                                                  \
    {                                                                          \
        const int k0 = (KC) * 8 + tig;                                         \
        const float4 wa = Wt[k0 * 2],       wb = Wt[k0 * 2 + 1];               \
        const float4 va = Wt[(k0 + 4) * 2], vb = Wt[(k0 + 4) * 2 + 1];         \
        float s00 = wb.z, s10 = wb.z, s20 = wb.z, s30 = wb.z;                  \
        float s01 = vb.z, s11 = vb.z, s21 = vb.z, s31 = vb.z;                  \
        s00 = fmaf(rb[0][0], wa.x, s00); s01 = fmaf(rb[0][0], va.x, s01);      \
        s10 = fmaf(rb[1][0], wa.x, s10); s11 = fmaf(rb[1][0], va.x, s11);      \
        s20 = fmaf(rb[2][0], wa.x, s20); s21 = fmaf(rb[2][0], va.x, s21);      \
        s30 = fmaf(rb[3][0], wa.x, s30); s31 = fmaf(rb[3][0], va.x, s31);      \
        s00 = fmaf(rb[0][1], wa.y, s00); s01 = fmaf(rb[0][1], va.y, s01);      \
        s10 = fmaf(rb[1][1], wa.y, s10); s11 = fmaf(rb[1][1], va.y, s11);      \
        s20 = fmaf(rb[2][1], wa.y, s20); s21 = fmaf(rb[2][1], va.y, s21);      \
        s30 = fmaf(rb[3][1], wa.y, s30); s31 = fmaf(rb[3][1], va.y, s31);      \
        s00 = fmaf(rb[0][2], wa.z, s00); s01 = fmaf(rb[0][2], va.z, s01);      \
        s10 = fmaf(rb[1][2], wa.z, s10); s11 = fmaf(rb[1][2], va.z, s11);      \
        s20 = fmaf(rb[2][2], wa.z, s20); s21 = fmaf(rb[2][2], va.z, s21);      \
        s30 = fmaf(rb[3][2], wa.z, s30); s31 = fmaf(rb[3][2], va.z, s31);      \
        s00 = fmaf(rb[0][3], wa.w, s00); s01 = fmaf(rb[0][3], va.w, s01);      \
        s10 = fmaf(rb[1][3], wa.w, s10); s11 = fmaf(rb[1][3], va.w, s11);      \
        s20 = fmaf(rb[2][3], wa.w, s20); s21 = fmaf(rb[2][3], va.w, s21);      \
        s30 = fmaf(rb[3][3], wa.w, s30); s31 = fmaf(rb[3][3], va.w, s31);      \
        s00 = fmaf(rb[0][4], wb.x, s00); s01 = fmaf(rb[0][4], vb.x, s01);      \
        s10 = fmaf(rb[1][4], wb.x, s10); s11 = fmaf(rb[1][4], vb.x, s11);      \
        s20 = fmaf(rb[2][4], wb.x, s20); s21 = fmaf(rb[2][4], vb.x, s21);      \
        s30 = fmaf(rb[3][4], wb.x, s30); s31 = fmaf(rb[3][4], vb.x, s31);      \
        s00 = fmaf(rb[0][5], wb.y, s00); s01 = fmaf(rb[0][5], vb.y, s01);      \
        s10 = fmaf(rb[1][5], wb.y, s10); s11 = fmaf(rb[1][5], vb.y, s11);      \
        s20 = fmaf(rb[2][5], wb.y, s20); s21 = fmaf(rb[2][5], vb.y, s21);      \
        s30 = fmaf(rb[3][5], wb.y, s30); s31 = fmaf(rb[3][5], vb.y, s31);      \
        D0[0] = f2tf32(silu_tanh(s00)); D0[1] = f2tf32(silu_tanh(s10));        \
        D0[2] = f2tf32(silu_tanh(s01)); D0[3] = f2tf32(silu_tanh(s11));        \
        D1[0] = f2tf32(silu_tanh(s20)); D1[1] = f2tf32(silu_tanh(s30));        \
        D1[2] = f2tf32(silu_tanh(s21)); D1[3] = f2tf32(silu_tanh(s31));        \
    }

    COMPUTE_A(0, Ac0, Ac1);

#pragma unroll
    for (int kc = 0; kc < 16; ++kc) {
        uint32_t An0[4], An1[4];
        if (kc < 15) COMPUTE_A(kc + 1, An0, An1);

        const float2* bp = Bf + (kc * 16 + sh * 8) * 32 + lane;
#pragma unroll
        for (int nt = 0; nt < 8; ++nt) {
            const float2 b = bp[nt * 32];
            const uint32_t b0 = __float_as_uint(b.x);
            const uint32_t b1 = __float_as_uint(b.y);
            asm volatile(
                "mma.sync.aligned.m16n8k8.row.col.f32.tf32.tf32.f32 "
                "{%0,%1,%2,%3}, {%4,%5,%6,%7}, {%8,%9}, {%0,%1,%2,%3};\n"
                : "+f"(acc[0][nt][0]), "+f"(acc[0][nt][1]),
                  "+f"(acc[0][nt][2]), "+f"(acc[0][nt][3])
                : "r"(Ac0[0]), "r"(Ac0[1]), "r"(Ac0[2]), "r"(Ac0[3]),
                  "r"(b0), "r"(b1));
            asm volatile(
                "mma.sync.aligned.m16n8k8.row.col.f32.tf32.tf32.f32 "
                "{%0,%1,%2,%3}, {%4,%5,%6,%7}, {%8,%9}, {%0,%1,%2,%3};\n"
                : "+f"(acc[1][nt][0]), "+f"(acc[1][nt][1]),
                  "+f"(acc[1][nt][2]), "+f"(acc[1][nt][3])
                : "r"(Ac1[0]), "r"(Ac1[1]), "r"(Ac1[2]), "r"(Ac1[3]),
                  "r"(b0), "r"(b1));
        }
        if (kc < 15) {
#pragma unroll
            for (int q = 0; q < 4; ++q) { Ac0[q] = An0[q]; Ac1[q] = An1[q]; }
        }
    }
#undef COMPUTE_A
    __syncthreads();      // Bf fully consumed; safe to overwrite with acc

    // ---- dump acc to SMEM (row-major, XOR row swizzle, fits in 64K) ------
#pragma unroll
    for (int mb = 0; mb < 2; ++mb)
#pragma unroll
        for (int h = 0; h < 2; ++h) {
            const int row = u * 32 + mb * 16 + g + 8 * h;
            const int xr = (row & 7) << 2;
            float* rp = accS + row * HID;
#pragma unroll
            for (int nt = 0; nt < 8; ++nt) {
                const int col = (sh * 64 + nt * 8 + 2 * tig) ^ xr;
                *(float2*)(rp + col) =
                    make_float2(acc[mb][nt][2 * h], acc[mb][nt][2 * h + 1]);
            }
        }
    __syncthreads();

    // ---- row-major epilogue (1 warp : 1 edge per iter) -------------------
#pragma unroll 2
    for (int it = 0; it < 16; ++it) {
        const int el = w * 16 + it;                 // 0..127
        const int e = base + el;
        const int xc = (lane * 4) ^ ((el & 7) << 2);
        const float4 av = *(const float4*)(accS + el * HID + xc);
        const float4 ta = *(const float4*)(g_TA + tyI[el] * HID + lane * 4);
        const float4 tb = *(const float4*)(g_TB + tyJ[el] * HID + lane * 4);
        float4 o;
        o.x = silu_exact(av.x + ta.x + tb.x);
        o.y = silu_exact(av.y + ta.y + tb.y);
        o.z = silu_exact(av.z + ta.z + tb.z);
        o.w = silu_exact(av.w + ta.w + tb.w);
        if (e < E) *(float4*)(out + e * HID + lane * 4) = o;
    }
}

// ---------------------------------------------------------------------------
extern "C" void kernel_launch(void* const* d_in, const int* in_sizes, int n_in,
                              void* d_out, int out_size) {
    const int*   x        = (const int*)d_in[0];
    const float* rbf      = (const float*)d_in[1];
    const int*   ei       = (const int*)d_in[2];
    const int*   ej       = (const int*)d_in[3];
    const int*   code_idx = (const int*)d_in[4];
    const float* codebook = (const float*)d_in[5];
    const float* W_rbf    = (const float*)d_in[6];
    const float* b_rbf    = (const float*)d_in[7];
    const float* W        = (const float*)d_in[8];
    const float* bias     = (const float*)d_in[9];
    float*       out      = (float*)d_out;

    const int E = in_sizes[2];

    static bool attr_set = false;
    if (!attr_set) {
        cudaFuncSetAttribute(edge_kernel,
                             cudaFuncAttributeMaxDynamicSharedMemorySize, SMEM_SZ);
        attr_set = true;
    }

    prep_kernel<<<160, 256>>>(code_idx, codebook, W, bias);
    edge_kernel<<<(E + TILE_E - 1) / TILE_E, 256, SMEM_SZ>>>(x, rbf, ei, ej,
                                                             W_rbf, b_rbf, out, E);
}

// round 11
// speedup vs baseline: 2.8156x; 1.0041x over previous
#include <cuda_runtime.h>
#include <cstdint>

// ===========================================================================
// SymbolicEmbeddingBlock — tf32 mma.sync, persistent CTAs, 2 CTAs/SM.
//   out[e] = silu( TA'[x[i[e]]] + TB[x[j[e]]] + r[e] @ W3 )   (bias in TA')
//   r[e]   = silu( rbf[e] @ W_rbf + b_rbf )        (phase-1 silu: tanh.approx)
// Grid = 296 persistent CTAs. Bf/Wt staged ONCE per CTA; loop over tiles.
// CTA tile = 128 edges x 128 cols; warp tile M=32 x N=64, A-frags in regs.
// acc -> dedicated 32KB SMEM buffer in two 64-row halves -> coalesced epilogue.
// ===========================================================================

#define HID    128
#define TILE_E 128

static __device__ float  g_TA[128 * HID];      // bias folded in
static __device__ float  g_TB[128 * HID];
static __device__ float2 g_Bf[16 * 16 * 32];   // [kc][nt][lane] {b0,b1}

// SMEM map (bytes) — no aliasing.
#define BF_OFF   0                      // 65536
#define ACC_OFF  65536                  // 32768 (64 rows x 128 cols f32)
#define WT_OFF   98304                  // 4096
#define TY_OFF   102400                 // tyI[128], tyJ[128] : 1024
#define SMEM_SZ  103424

__device__ __forceinline__ uint32_t f2tf32(float x) {
    uint32_t u;
    asm("cvt.rna.tf32.f32 %0, %1;" : "=r"(u) : "f"(x));
    return u;
}
__device__ __forceinline__ float silu_exact(float x) {
    return __fdividef(x, 1.0f + __expf(-x));
}
__device__ __forceinline__ float silu_tanh(float x) {    // 1 MUFU
    float h = 0.5f * x, t;
    asm("tanh.approx.f32 %0, %1;" : "=f"(t) : "f"(h));
    return fmaf(h, t, h);
}

// ---------------------------------------------------------------------------
// prep (merged): blocks 0-127 -> TA/TB tables; blocks 128-159 -> B fragments.
// ---------------------------------------------------------------------------
__global__ void prep_kernel(const int* __restrict__ code_idx,
                            const float* __restrict__ codebook,
                            const float* __restrict__ W,
                            const float* __restrict__ bias) {
    const int tid = threadIdx.x;
    if (blockIdx.x >= 128) {
        const int idx = (blockIdx.x - 128) * 256 + tid;     // 0..8191
        const int l = idx & 31, nt = (idx >> 5) & 15, kc = idx >> 9;
        const int g = l >> 2, tg = l & 3;
        const int k = kc * 8 + tg, n = nt * 8 + g;
        float2 v;
        v.x = __uint_as_float(f2tf32(W[(256 + k) * HID + n]));
        v.y = __uint_as_float(f2tf32(W[(256 + k + 4) * HID + n]));
        g_Bf[idx] = v;
        return;
    }
    __shared__ float row[HID];
    const int t = blockIdx.x;
    if (tid < HID) {
        int p = tid >> 4, s2 = tid & 15;
        row[tid] = codebook[code_idx[t * 8 + p] * 16 + s2];
    }
    __syncthreads();
    const float* Wb = (tid < HID) ? W : (W + HID * HID);
    const int c = tid & (HID - 1);
    float a0 = 0.f, a1 = 0.f, a2 = 0.f, a3 = 0.f;
#pragma unroll
    for (int d = 0; d < HID; d += 4) {
        a0 = fmaf(row[d],     Wb[(d)     * HID + c], a0);
        a1 = fmaf(row[d + 1], Wb[(d + 1) * HID + c], a1);
        a2 = fmaf(row[d + 2], Wb[(d + 2) * HID + c], a2);
        a3 = fmaf(row[d + 3], Wb[(d + 3) * HID + c], a3);
    }
    const float acc = (a0 + a1) + (a2 + a3);
    if (tid < HID) g_TA[t * HID + c] = acc + bias[c];
    else           g_TB[t * HID + c] = acc;
}

// ---------------------------------------------------------------------------
// edge kernel: persistent, 256 threads, 8 warps, 2 CTAs/SM.
// ---------------------------------------------------------------------------
__global__ __launch_bounds__(256, 2)
void edge_kernel(const int* __restrict__ x, const float* __restrict__ rbf,
                 const int* __restrict__ ei, const int* __restrict__ ej,
                 const float* __restrict__ W_rbf, const float* __restrict__ b_rbf,
                 float* __restrict__ out, int E, int n_tiles) {
    extern __shared__ char sm[];
    float2* Bf   = (float2*)(sm + BF_OFF);
    float*  accS = (float*)(sm + ACC_OFF);
    float4* Wt   = (float4*)(sm + WT_OFF);
    int*    tyI  = (int*)(sm + TY_OFF);
    int*    tyJ  = (int*)(sm + TY_OFF + 512);

    const int tid = threadIdx.x, lane = tid & 31, w = tid >> 5;
    const int g = lane >> 2, tig = lane & 3;
    const int u = w & 3, sh = w >> 2;

    // ---- one-time staging: Bf + Wt ---------------------------------------
    {
        const float4* gB = (const float4*)g_Bf;
        float4* sB = (float4*)(sm + BF_OFF);
#pragma unroll
        for (int i = 0; i < 16; ++i) sB[tid + i * 256] = gB[tid + i * 256];
        if (tid < HID) {
            const int k = tid;
            float4 a, b;
            a.x = W_rbf[0 * HID + k]; a.y = W_rbf[1 * HID + k];
            a.z = W_rbf[2 * HID + k]; a.w = W_rbf[3 * HID + k];
            b.x = W_rbf[4 * HID + k]; b.y = W_rbf[5 * HID + k];
            b.z = b_rbf[k];           b.w = 0.0f;
            Wt[k * 2 + 0] = a;
            Wt[k * 2 + 1] = b;
        }
    }
    __syncthreads();

    for (int t = blockIdx.x; t < n_tiles; t += gridDim.x) {
        const int base = t * TILE_E;

        // stage node types for this tile (read after the next barrier)
        if (tid < TILE_E) {
            int e = base + tid;
            if (e >= E) e = E - 1;
            tyI[tid] = x[ei[e]];
            tyJ[tid] = x[ej[e]];
        }

        // this thread's 4 edges (rows g, g+8 of m-blocks 2u, 2u+1)
        float rb[4][6];
#pragma unroll
        for (int q = 0; q < 4; ++q) {
            int e = base + u * 32 + g + q * 8;
            if (e >= E) e = E - 1;
            const float2 p0 = *(const float2*)(rbf + e * 6);
            const float2 p1 = *(const float2*)(rbf + e * 6 + 2);
            const float2 p2 = *(const float2*)(rbf + e * 6 + 4);
            rb[q][0] = p0.x; rb[q][1] = p0.y; rb[q][2] = p1.x;
            rb[q][3] = p1.y; rb[q][4] = p2.x; rb[q][5] = p2.y;
        }

        // ---- main loop: pipelined A-compute + mma ------------------------
        float acc[2][8][4];
#pragma unroll
        for (int mb = 0; mb < 2; ++mb)
#pragma unroll
            for (int nt = 0; nt < 8; ++nt)
#pragma unroll
                for (int q = 0; q < 4; ++q) acc[mb][nt][q] = 0.0f;

        uint32_t Ac0[4], Ac1[4];

#define COMPUTE_A(KC, D0, D1)                                                  \
    {                                                                          \
        const int k0 = (KC) * 8 + tig;                                         \
        const float4 wa = Wt[k0 * 2],       wb = Wt[k0 * 2 + 1];               \
        const float4 va = Wt[(k0 + 4) * 2], vb = Wt[(k0 + 4) * 2 + 1];         \
        float s00 = wb.z, s10 = wb.z, s20 = wb.z, s30 = wb.z;                  \
        float s01 = vb.z, s11 = vb.z, s21 = vb.z, s31 = vb.z;                  \
        s00 = fmaf(rb[0][0], wa.x, s00); s01 = fmaf(rb[0][0], va.x, s01);      \
        s10 = fmaf(rb[1][0], wa.x, s10); s11 = fmaf(rb[1][0], va.x, s11);      \
        s20 = fmaf(rb[2][0], wa.x, s20); s21 = fmaf(rb[2][0], va.x, s21);      \
        s30 = fmaf(rb[3][0], wa.x, s30); s31 = fmaf(rb[3][0], va.x, s31);      \
        s00 = fmaf(rb[0][1], wa.y, s00); s01 = fmaf(rb[0][1], va.y, s01);      \
        s10 = fmaf(rb[1][1], wa.y, s10); s11 = fmaf(rb[1][1], va.y, s11);      \
        s20 = fmaf(rb[2][1], wa.y, s20); s21 = fmaf(rb[2][1], va.y, s21);      \
        s30 = fmaf(rb[3][1], wa.y, s30); s31 = fmaf(rb[3][1], va.y, s31);      \
        s00 = fmaf(rb[0][2], wa.z, s00); s01 = fmaf(rb[0][2], va.z, s01);      \
        s10 = fmaf(rb[1][2], wa.z, s10); s11 = fmaf(rb[1][2], va.z, s11);      \
        s20 = fmaf(rb[2][2], wa.z, s20); s21 = fmaf(rb[2][2], va.z, s21);      \
        s30 = fmaf(rb[3][2], wa.z, s30); s31 = fmaf(rb[3][2], va.z, s31);      \
        s00 = fmaf(rb[0][3], wa.w, s00); s01 = fmaf(rb[0][3], va.w, s01);      \
        s10 = fmaf(rb[1][3], wa.w, s10); s11 = fmaf(rb[1][3], va.w, s11);      \
        s20 = fmaf(rb[2][3], wa.w, s20); s21 = fmaf(rb[2][3], va.w, s21);      \
        s30 = fmaf(rb[3][3], wa.w, s30); s31 = fmaf(rb[3][3], va.w, s31);      \
        s00 = fmaf(rb[0][4], wb.x, s00); s01 = fmaf(rb[0][4], vb.x, s01);      \
        s10 = fmaf(rb[1][4], wb.x, s10); s11 = fmaf(rb[1][4], vb.x, s11);      \
        s20 = fmaf(rb[2][4], wb.x, s20); s21 = fmaf(rb[2][4], vb.x, s21);      \
        s30 = fmaf(rb[3][4], wb.x, s30); s31 = fmaf(rb[3][4], vb.x, s31);      \
        s00 = fmaf(rb[0][5], wb.y, s00); s01 = fmaf(rb[0][5], vb.y, s01);      \
        s10 = fmaf(rb[1][5], wb.y, s10); s11 = fmaf(rb[1][5], vb.y, s11);      \
        s20 = fmaf(rb[2][5], wb.y, s20); s21 = fmaf(rb[2][5], vb.y, s21);      \
        s30 = fmaf(rb[3][5], wb.y, s30); s31 = fmaf(rb[3][5], vb.y, s31);      \
        D0[0] = f2tf32(silu_tanh(s00)); D0[1] = f2tf32(silu_tanh(s10));        \
        D0[2] = f2tf32(silu_tanh(s01)); D0[3] = f2tf32(silu_tanh(s11));        \
        D1[0] = f2tf32(silu_tanh(s20)); D1[1] = f2tf32(silu_tanh(s30));        \
        D1[2] = f2tf32(silu_tanh(s21)); D1[3] = f2tf32(silu_tanh(s31));        \
    }

        COMPUTE_A(0, Ac0, Ac1);

        const float2* bp = Bf + (sh * 8) * 32 + lane;
#pragma unroll
        for (int kc = 0; kc < 16; ++kc) {
            uint32_t An0[4], An1[4];
            if (kc < 15) COMPUTE_A(kc + 1, An0, An1);
#pragma unroll
            for (int nt = 0; nt < 8; ++nt) {
                const float2 b = bp[nt * 32];
                const uint32_t b0 = __float_as_uint(b.x);
                const uint32_t b1 = __float_as_uint(b.y);
                asm("mma.sync.aligned.m16n8k8.row.col.f32.tf32.tf32.f32 "
                    "{%0,%1,%2,%3}, {%4,%5,%6,%7}, {%8,%9}, {%0,%1,%2,%3};\n"
                    : "+f"(acc[0][nt][0]), "+f"(acc[0][nt][1]),
                      "+f"(acc[0][nt][2]), "+f"(acc[0][nt][3])
                    : "r"(Ac0[0]), "r"(Ac0[1]), "r"(Ac0[2]), "r"(Ac0[3]),
                      "r"(b0), "r"(b1));
                asm("mma.sync.aligned.m16n8k8.row.col.f32.tf32.tf32.f32 "
                    "{%0,%1,%2,%3}, {%4,%5,%6,%7}, {%8,%9}, {%0,%1,%2,%3};\n"
                    : "+f"(acc[1][nt][0]), "+f"(acc[1][nt][1]),
                      "+f"(acc[1][nt][2]), "+f"(acc[1][nt][3])
                    : "r"(Ac1[0]), "r"(Ac1[1]), "r"(Ac1[2]), "r"(Ac1[3]),
                      "r"(b0), "r"(b1));
            }
            bp += 512;
            if (kc < 15) {
#pragma unroll
                for (int q = 0; q < 4; ++q) { Ac0[q] = An0[q]; Ac1[q] = An1[q]; }
            }
        }
#undef COMPUTE_A

        // ---- two-half dump + epilogue ------------------------------------
#pragma unroll
        for (int h = 0; h < 2; ++h) {
            __syncthreads();   // acc regs final / previous epilogue half done
            if ((u >> 1) == h) {
                // dump this warp's 32 rows into the 64-row half buffer
#pragma unroll
                for (int mb = 0; mb < 2; ++mb)
#pragma unroll
                    for (int hh = 0; hh < 2; ++hh) {
                        const int rowl = (u & 1) * 32 + mb * 16 + g + 8 * hh;
                        const int xr = g << 2;
                        float* rp = accS + rowl * HID;
#pragma unroll
                        for (int nt = 0; nt < 8; ++nt) {
                            const int col = (sh * 64 + nt * 8 + 2 * tig) ^ xr;
                            *(float2*)(rp + col) = make_float2(
                                acc[mb][nt][2 * hh], acc[mb][nt][2 * hh + 1]);
                        }
                    }
            }
            __syncthreads();
            // epilogue: 8 rows per warp, coalesced
#pragma unroll 2
            for (int it = 0; it < 8; ++it) {
                const int ell = w * 8 + it;            // 0..63 in half
                const int el = h * 64 + ell;           // 0..127 in tile
                const int e = base + el;
                const int xc = (lane * 4) ^ ((ell & 7) << 2);
                const float4 av = *(const float4*)(accS + ell * HID + xc);
                const float4 ta = *(const float4*)(g_TA + tyI[el] * HID + lane * 4);
                const float4 tb = *(const float4*)(g_TB + tyJ[el] * HID + lane * 4);
                float4 o;
                o.x = silu_exact(av.x + ta.x + tb.x);
                o.y = silu_exact(av.y + ta.y + tb.y);
                o.z = silu_exact(av.z + ta.z + tb.z);
                o.w = silu_exact(av.w + ta.w + tb.w);
                if (e < E) *(float4*)(out + e * HID + lane * 4) = o;
            }
        }
        __syncthreads();   // ty/accS safe to rewrite next iteration
    }
}

// ---------------------------------------------------------------------------
extern "C" void kernel_launch(void* const* d_in, const int* in_sizes, int n_in,
                              void* d_out, int out_size) {
    const int*   x        = (const int*)d_in[0];
    const float* rbf      = (const float*)d_in[1];
    const int*   ei       = (const int*)d_in[2];
    const int*   ej       = (const int*)d_in[3];
    const int*   code_idx = (const int*)d_in[4];
    const float* codebook = (const float*)d_in[5];
    const float* W_rbf    = (const float*)d_in[6];
    const float* b_rbf    = (const float*)d_in[7];
    const float* W        = (const float*)d_in[8];
    const float* bias     = (const float*)d_in[9];
    float*       out      = (float*)d_out;

    const int E = in_sizes[2];
    const int n_tiles = (E + TILE_E - 1) / TILE_E;

    static bool attr_set = false;
    if (!attr_set) {
        cudaFuncSetAttribute(edge_kernel,
                             cudaFuncAttributeMaxDynamicSharedMemorySize, SMEM_SZ);
        attr_set = true;
    }

    prep_kernel<<<160, 256>>>(code_idx, codebook, W, bias);
    edge_kernel<<<296, 256, SMEM_SZ>>>(x, rbf, ei, ej, W_rbf, b_rbf,
                                       out, E, n_tiles);
}

// round 12
// speedup vs baseline: 2.9320x; 1.0413x over previous
#include <cuda_runtime.h>
#include <cstdint>

// ===========================================================================
// SymbolicEmbeddingBlock — tf32 mma.sync, persistent, M=16xN=128 warp tile.
//   out[e] = silu( TA'[x[i[e]]] + TB[x[j[e]]] + r[e] @ W3 )   (bias in TA')
//   r[e]   = silu( rbf[e] @ W_rbf + b_rbf )        (phase-1 silu: tanh.approx)
// Grid = 296 persistent CTAs, 256 thr, 2 CTAs/SM. Bf/Wt staged once.
// Warp tile M=16 x N=128 -> every A-fragment computed exactly ONCE.
// acc -> 32KB SMEM buffer in two 64-row halves -> coalesced epilogue.
// ===========================================================================

#define HID    128
#define TILE_E 128

static __device__ float  g_TA[128 * HID];      // bias folded in
static __device__ float  g_TB[128 * HID];
static __device__ float2 g_Bf[16 * 16 * 32];   // [kc][nt][lane] {b0,b1}

// SMEM map (bytes) — no aliasing.
#define BF_OFF   0                      // 65536
#define ACC_OFF  65536                  // 32768 (64 rows x 128 cols f32)
#define WT_OFF   98304                  // 4096
#define TY_OFF   102400                 // tyI[128], tyJ[128] : 1024
#define SMEM_SZ  103424

__device__ __forceinline__ uint32_t f2tf32(float x) {
    uint32_t u;
    asm("cvt.rna.tf32.f32 %0, %1;" : "=r"(u) : "f"(x));
    return u;
}
__device__ __forceinline__ float silu_exact(float x) {
    return __fdividef(x, 1.0f + __expf(-x));
}
__device__ __forceinline__ float silu_tanh(float x) {    // 1 MUFU
    float h = 0.5f * x, t;
    asm("tanh.approx.f32 %0, %1;" : "=f"(t) : "f"(h));
    return fmaf(h, t, h);
}

// ---------------------------------------------------------------------------
// prep (merged): blocks 0-127 -> TA/TB tables; blocks 128-159 -> B fragments.
// ---------------------------------------------------------------------------
__global__ void prep_kernel(const int* __restrict__ code_idx,
                            const float* __restrict__ codebook,
                            const float* __restrict__ W,
                            const float* __restrict__ bias) {
    const int tid = threadIdx.x;
    if (blockIdx.x >= 128) {
        const int idx = (blockIdx.x - 128) * 256 + tid;     // 0..8191
        const int l = idx & 31, nt = (idx >> 5) & 15, kc = idx >> 9;
        const int g = l >> 2, tg = l & 3;
        const int k = kc * 8 + tg, n = nt * 8 + g;
        float2 v;
        v.x = __uint_as_float(f2tf32(W[(256 + k) * HID + n]));
        v.y = __uint_as_float(f2tf32(W[(256 + k + 4) * HID + n]));
        g_Bf[idx] = v;
        return;
    }
    __shared__ float row[HID];
    const int t = blockIdx.x;
    if (tid < HID) {
        int p = tid >> 4, s2 = tid & 15;
        row[tid] = codebook[code_idx[t * 8 + p] * 16 + s2];
    }
    __syncthreads();
    const float* Wb = (tid < HID) ? W : (W + HID * HID);
    const int c = tid & (HID - 1);
    float a0 = 0.f, a1 = 0.f, a2 = 0.f, a3 = 0.f;
#pragma unroll
    for (int d = 0; d < HID; d += 4) {
        a0 = fmaf(row[d],     Wb[(d)     * HID + c], a0);
        a1 = fmaf(row[d + 1], Wb[(d + 1) * HID + c], a1);
        a2 = fmaf(row[d + 2], Wb[(d + 2) * HID + c], a2);
        a3 = fmaf(row[d + 3], Wb[(d + 3) * HID + c], a3);
    }
    const float acc = (a0 + a1) + (a2 + a3);
    if (tid < HID) g_TA[t * HID + c] = acc + bias[c];
    else           g_TB[t * HID + c] = acc;
}

// ---------------------------------------------------------------------------
// edge kernel: persistent, 256 threads, 8 warps, 2 CTAs/SM.
// Warp w owns edge rows [w*16, w*16+16); full 128-col width.
// ---------------------------------------------------------------------------
__global__ __launch_bounds__(256, 2)
void edge_kernel(const int* __restrict__ x, const float* __restrict__ rbf,
                 const int* __restrict__ ei, const int* __restrict__ ej,
                 const float* __restrict__ W_rbf, const float* __restrict__ b_rbf,
                 float* __restrict__ out, int E, int n_tiles) {
    extern __shared__ char sm[];
    float2* Bf   = (float2*)(sm + BF_OFF);
    float*  accS = (float*)(sm + ACC_OFF);
    float4* Wt   = (float4*)(sm + WT_OFF);
    int*    tyI  = (int*)(sm + TY_OFF);
    int*    tyJ  = (int*)(sm + TY_OFF + 512);

    const int tid = threadIdx.x, lane = tid & 31, w = tid >> 5;
    const int g = lane >> 2, tig = lane & 3;

    // ---- one-time staging: Bf + Wt ---------------------------------------
    {
        const float4* gB = (const float4*)g_Bf;
        float4* sB = (float4*)(sm + BF_OFF);
#pragma unroll
        for (int i = 0; i < 16; ++i) sB[tid + i * 256] = gB[tid + i * 256];
        if (tid < HID) {
            const int k = tid;
            float4 a, b;
            a.x = W_rbf[0 * HID + k]; a.y = W_rbf[1 * HID + k];
            a.z = W_rbf[2 * HID + k]; a.w = W_rbf[3 * HID + k];
            b.x = W_rbf[4 * HID + k]; b.y = W_rbf[5 * HID + k];
            b.z = b_rbf[k];           b.w = 0.0f;
            Wt[k * 2 + 0] = a;
            Wt[k * 2 + 1] = b;
        }
    }
    __syncthreads();

    for (int t = blockIdx.x; t < n_tiles; t += gridDim.x) {
        const int base = t * TILE_E;

        // stage node types for this tile
        if (tid < TILE_E) {
            int e = base + tid;
            if (e >= E) e = E - 1;
            tyI[tid] = x[ei[e]];
            tyJ[tid] = x[ej[e]];
        }

        // this thread's 2 edges (rows g, g+8 of warp's 16-row block)
        float rb[2][6];
#pragma unroll
        for (int q = 0; q < 2; ++q) {
            int e = base + w * 16 + g + q * 8;
            if (e >= E) e = E - 1;
            const float2 p0 = *(const float2*)(rbf + e * 6);
            const float2 p1 = *(const float2*)(rbf + e * 6 + 2);
            const float2 p2 = *(const float2*)(rbf + e * 6 + 4);
            rb[q][0] = p0.x; rb[q][1] = p0.y; rb[q][2] = p1.x;
            rb[q][3] = p1.y; rb[q][4] = p2.x; rb[q][5] = p2.y;
        }

        // ---- main loop: pipelined A-compute + mma ------------------------
        float acc[16][4];
#pragma unroll
        for (int nt = 0; nt < 16; ++nt)
#pragma unroll
            for (int q = 0; q < 4; ++q) acc[nt][q] = 0.0f;

        uint32_t Ac[4];

        // A-fragment: 2 edges x 2 k-cols -> a0..a3 of one m16 tile
#define COMPUTE_A(KC, D)                                                       \
    {                                                                          \
        const int k0 = (KC) * 8 + tig;                                         \
        const float4 wa = Wt[k0 * 2],       wb = Wt[k0 * 2 + 1];               \
        const float4 va = Wt[(k0 + 4) * 2], vb = Wt[(k0 + 4) * 2 + 1];         \
        float s00 = wb.z, s10 = wb.z, s01 = vb.z, s11 = vb.z;                  \
        s00 = fmaf(rb[0][0], wa.x, s00); s01 = fmaf(rb[0][0], va.x, s01);      \
        s10 = fmaf(rb[1][0], wa.x, s10); s11 = fmaf(rb[1][0], va.x, s11);      \
        s00 = fmaf(rb[0][1], wa.y, s00); s01 = fmaf(rb[0][1], va.y, s01);      \
        s10 = fmaf(rb[1][1], wa.y, s10); s11 = fmaf(rb[1][1], va.y, s11);      \
        s00 = fmaf(rb[0][2], wa.z, s00); s01 = fmaf(rb[0][2], va.z, s01);      \
        s10 = fmaf(rb[1][2], wa.z, s10); s11 = fmaf(rb[1][2], va.z, s11);      \
        s00 = fmaf(rb[0][3], wa.w, s00); s01 = fmaf(rb[0][3], va.w, s01);      \
        s10 = fmaf(rb[1][3], wa.w, s10); s11 = fmaf(rb[1][3], va.w, s11);      \
        s00 = fmaf(rb[0][4], wb.x, s00); s01 = fmaf(rb[0][4], vb.x, s01);      \
        s10 = fmaf(rb[1][4], wb.x, s10); s11 = fmaf(rb[1][4], vb.x, s11);      \
        s00 = fmaf(rb[0][5], wb.y, s00); s01 = fmaf(rb[0][5], vb.y, s01);      \
        s10 = fmaf(rb[1][5], wb.y, s10); s11 = fmaf(rb[1][5], vb.y, s11);      \
        D[0] = f2tf32(silu_tanh(s00));  /* row g,   k tig   */                 \
        D[1] = f2tf32(silu_tanh(s10));  /* row g+8, k tig   */                 \
        D[2] = f2tf32(silu_tanh(s01));  /* row g,   k tig+4 */                 \
        D[3] = f2tf32(silu_tanh(s11));  /* row g+8, k tig+4 */                 \
    }

        COMPUTE_A(0, Ac);

        const float2* bp = Bf + lane;
#pragma unroll
        for (int kc = 0; kc < 16; ++kc) {
            uint32_t An[4];
            if (kc < 15) COMPUTE_A(kc + 1, An);
#pragma unroll
            for (int nt = 0; nt < 16; ++nt) {
                const float2 b = bp[nt * 32];
                asm("mma.sync.aligned.m16n8k8.row.col.f32.tf32.tf32.f32 "
                    "{%0,%1,%2,%3}, {%4,%5,%6,%7}, {%8,%9}, {%0,%1,%2,%3};\n"
                    : "+f"(acc[nt][0]), "+f"(acc[nt][1]),
                      "+f"(acc[nt][2]), "+f"(acc[nt][3])
                    : "r"(Ac[0]), "r"(Ac[1]), "r"(Ac[2]), "r"(Ac[3]),
                      "r"(__float_as_uint(b.x)), "r"(__float_as_uint(b.y)));
            }
            bp += 512;
            if (kc < 15) {
#pragma unroll
                for (int q = 0; q < 4; ++q) Ac[q] = An[q];
            }
        }
#undef COMPUTE_A

        // ---- two-half dump + epilogue ------------------------------------
#pragma unroll
        for (int h = 0; h < 2; ++h) {
            __syncthreads();   // previous half fully consumed
            if ((w >> 2) == h) {
                // dump this warp's 16 rows into the 64-row half buffer
                const int rw = (w & 3) * 16;     // local row base in half
                const int xr = g << 2;
#pragma unroll
                for (int hh = 0; hh < 2; ++hh) {
                    float* rp = accS + (rw + g + 8 * hh) * HID;
#pragma unroll
                    for (int nt = 0; nt < 16; ++nt) {
                        const int col = (nt * 8 + 2 * tig) ^ xr;
                        *(float2*)(rp + col) =
                            make_float2(acc[nt][2 * hh], acc[nt][2 * hh + 1]);
                    }
                }
            }
            __syncthreads();
            // epilogue: 8 rows per warp, coalesced
#pragma unroll 2
            for (int it = 0; it < 8; ++it) {
                const int ell = w * 8 + it;            // 0..63 in half
                const int el = h * 64 + ell;           // 0..127 in tile
                const int e = base + el;
                const int xc = (lane * 4) ^ ((ell & 7) << 2);
                const float4 av = *(const float4*)(accS + ell * HID + xc);
                const float4 ta = *(const float4*)(g_TA + tyI[el] * HID + lane * 4);
                const float4 tb = *(const float4*)(g_TB + tyJ[el] * HID + lane * 4);
                float4 o;
                o.x = silu_exact(av.x + ta.x + tb.x);
                o.y = silu_exact(av.y + ta.y + tb.y);
                o.z = silu_exact(av.z + ta.z + tb.z);
                o.w = silu_exact(av.w + ta.w + tb.w);
                if (e < E) *(float4*)(out + e * HID + lane * 4) = o;
            }
        }
        __syncthreads();   // ty/accS safe to rewrite next iteration
    }
}

// ---------------------------------------------------------------------------
extern "C" void kernel_launch(void* const* d_in, const int* in_sizes, int n_in,
                              void* d_out, int out_size) {
    const int*   x        = (const int*)d_in[0];
    const float* rbf      = (const float*)d_in[1];
    const int*   ei       = (const int*)d_in[2];
    const int*   ej       = (const int*)d_in[3];
    const int*   code_idx = (const int*)d_in[4];
    const float* codebook = (const float*)d_in[5];
    const float* W_rbf    = (const float*)d_in[6];
    const float* b_rbf    = (const float*)d_in[7];
    const float* W        = (const float*)d_in[8];
    const float* bias     = (const float*)d_in[9];
    float*       out      = (float*)d_out;

    const int E = in_sizes[2];
    const int n_tiles = (E + TILE_E - 1) / TILE_E;

    static bool attr_set = false;
    if (!attr_set) {
        cudaFuncSetAttribute(edge_kernel,
                             cudaFuncAttributeMaxDynamicSharedMemorySize, SMEM_SZ);
        attr_set = true;
    }

    prep_kernel<<<160, 256>>>(code_idx, codebook, W, bias);
    edge_kernel<<<296, 256, SMEM_SZ>>>(x, rbf, ei, ej, W_rbf, b_rbf,
                                       out, E, n_tiles);
}